// round 1
// baseline (speedup 1.0000x reference)
#include <cuda_runtime.h>
#include <math.h>

#define B_ 4
#define C_ 512
#define L_ 2048
#define H_ 8
#define D_ 64
#define G_ 8
#define CPG_ (C_/G_)          // 64 channels per group
#define EPS_ 1e-5f

// ---------------- scratch (static device allocations; no cudaMalloc) --------
__device__ float g_s[B_ * C_];                         // per-channel scale (w*rstd)
__device__ float g_t[B_ * C_];                         // per-channel shift
__device__ float g_qkv[(size_t)B_ * 3 * C_ * L_];      // 50 MB
__device__ float g_scores[(size_t)B_ * H_ * L_ * L_];  // 537 MB
__device__ float g_att[(size_t)B_ * C_ * L_];          // 17 MB

// ---------------- fast exp (avoid MUFU bottleneck) --------------------------
__device__ __forceinline__ float fast_exp(float x) {
    float z = x * 1.4426950408889634f;       // x * log2(e)
    z = fmaxf(z, -126.0f);
    float zi = rintf(z);
    int   i  = (int)zi;
    float y  = (z - zi) * 0.6931471805599453f;   // |y| <= 0.347
    float r  = 8.3333333e-3f;                    // 1/120
    r = fmaf(r, y, 4.1666667e-2f);               // 1/24
    r = fmaf(r, y, 1.6666667e-1f);               // 1/6
    r = fmaf(r, y, 0.5f);
    r = fmaf(r, y, 1.0f);
    r = fmaf(r, y, 1.0f);                        // e^y
    return __int_as_float(__float_as_int(r) + (i << 23));  // * 2^i
}

// ---------------- 1) GroupNorm stats -> per-channel affine ------------------
__global__ __launch_bounds__(256) void gn_stats_kernel(
    const float* __restrict__ x, const float* __restrict__ nw,
    const float* __restrict__ nb)
{
    int bg = blockIdx.x;
    int b = bg / G_, g = bg % G_;
    const float* xp = x + ((size_t)b * C_ + (size_t)g * CPG_) * L_;
    const int NE = CPG_ * L_;                     // 131072
    float sum = 0.f, sq = 0.f;
    for (int i = threadIdx.x; i < NE; i += 256) {
        float v = xp[i];
        sum += v; sq = fmaf(v, v, sq);
    }
    __shared__ float ssum[256], ssq[256];
    ssum[threadIdx.x] = sum; ssq[threadIdx.x] = sq;
    __syncthreads();
    for (int off = 128; off > 0; off >>= 1) {
        if (threadIdx.x < off) {
            ssum[threadIdx.x] += ssum[threadIdx.x + off];
            ssq[threadIdx.x]  += ssq[threadIdx.x + off];
        }
        __syncthreads();
    }
    float mean = ssum[0] * (1.0f / NE);
    float var  = ssq[0] * (1.0f / NE) - mean * mean;
    float rstd = rsqrtf(var + EPS_);
    if (threadIdx.x < CPG_) {
        int c = g * CPG_ + threadIdx.x;
        float s = nw[c] * rstd;
        g_s[b * C_ + c] = s;
        g_t[b * C_ + c] = nb[c] - mean * s;
    }
}

// ---------------- 2) SGEMM  C[b] = A(MxK,row) * B[b](KxN,row) + bias --------
// FOLD: B-operand element = x*s[c]+t[c] (groupnorm folded in)
// RESID: epilogue adds resid[b][m][n]
template<bool FOLD, bool RESID>
__global__ __launch_bounds__(256) void sgemm_wx_kernel(
    const float* __restrict__ A, const float* __restrict__ Bm,
    const float* __restrict__ bias, const float* __restrict__ resid,
    float* __restrict__ Cm, int M, int N, int K)
{
    int bz = blockIdx.z;
    const float* Bp = Bm + (size_t)bz * K * N;
    float*       Cp = Cm + (size_t)bz * M * N;
    const float* Rp = RESID ? (resid + (size_t)bz * M * N) : nullptr;
    const float* sp = FOLD ? (g_s + bz * C_) : nullptr;
    const float* tp = FOLD ? (g_t + bz * C_) : nullptr;

    int m0 = blockIdx.y * 128, n0 = blockIdx.x * 128;
    __shared__ float As[8][128];
    __shared__ float Bs[8][128];

    int tid = threadIdx.x;
    int tx = tid % 16, ty = tid / 16;     // 8x8 micro-tile
    int ar = tid / 2,  ac = (tid % 2) * 4;      // A: 128 rows x 8 k
    int bk = tid / 32, bn = (tid % 32) * 4;     // B: 8 k x 128 n

    float acc[8][8];
#pragma unroll
    for (int i = 0; i < 8; i++)
#pragma unroll
        for (int j = 0; j < 8; j++) acc[i][j] = 0.f;

    for (int k0 = 0; k0 < K; k0 += 8) {
        float4 av = *(const float4*)&A[(size_t)(m0 + ar) * K + k0 + ac];
        float4 bv = *(const float4*)&Bp[(size_t)(k0 + bk) * N + n0 + bn];
        if (FOLD) {
            float ss = sp[k0 + bk], tt = tp[k0 + bk];
            bv.x = fmaf(bv.x, ss, tt); bv.y = fmaf(bv.y, ss, tt);
            bv.z = fmaf(bv.z, ss, tt); bv.w = fmaf(bv.w, ss, tt);
        }
        __syncthreads();
        As[ac + 0][ar] = av.x; As[ac + 1][ar] = av.y;
        As[ac + 2][ar] = av.z; As[ac + 3][ar] = av.w;
        *(float4*)&Bs[bk][bn] = bv;
        __syncthreads();
#pragma unroll
        for (int kk = 0; kk < 8; kk++) {
            float a[8], bb[8];
            *(float4*)&a[0]  = *(const float4*)&As[kk][ty * 8];
            *(float4*)&a[4]  = *(const float4*)&As[kk][ty * 8 + 4];
            *(float4*)&bb[0] = *(const float4*)&Bs[kk][tx * 8];
            *(float4*)&bb[4] = *(const float4*)&Bs[kk][tx * 8 + 4];
#pragma unroll
            for (int i = 0; i < 8; i++)
#pragma unroll
                for (int j = 0; j < 8; j++)
                    acc[i][j] = fmaf(a[i], bb[j], acc[i][j]);
        }
    }

#pragma unroll
    for (int i = 0; i < 8; i++) {
        int m = m0 + ty * 8 + i;
        float bvv = bias[m];
        size_t base = (size_t)m * N + n0 + tx * 8;
#pragma unroll
        for (int v = 0; v < 2; v++) {
            float4 o;
            o.x = acc[i][v * 4 + 0] + bvv; o.y = acc[i][v * 4 + 1] + bvv;
            o.z = acc[i][v * 4 + 2] + bvv; o.w = acc[i][v * 4 + 3] + bvv;
            if (RESID) {
                float4 r = *(const float4*)&Rp[base + v * 4];
                o.x += r.x; o.y += r.y; o.z += r.z; o.w += r.w;
            }
            *(float4*)&Cp[base + v * 4] = o;
        }
    }
}

// ---------------- 3) scores: S[z][l][k] = scale * sum_d q[d][l]*k[d][k] -----
__global__ __launch_bounds__(256) void scores_kernel()
{
    int z = blockIdx.z;
    int b = z / H_, h = z % H_;
    const float* qp = g_qkv + (size_t)b * 3 * C_ * L_ + (size_t)(h * D_) * L_;
    const float* kp = qp + (size_t)C_ * L_;
    float* Sp = g_scores + (size_t)z * L_ * L_;

    int m0 = blockIdx.y * 128, n0 = blockIdx.x * 128;
    __shared__ float As[8][128];
    __shared__ float Bs[8][128];

    int tid = threadIdx.x;
    int tx = tid % 16, ty = tid / 16;
    int lk = tid / 32, ln = (tid % 32) * 4;

    float acc[8][8];
#pragma unroll
    for (int i = 0; i < 8; i++)
#pragma unroll
        for (int j = 0; j < 8; j++) acc[i][j] = 0.f;

    for (int k0 = 0; k0 < D_; k0 += 8) {
        float4 av = *(const float4*)&qp[(size_t)(k0 + lk) * L_ + m0 + ln];
        float4 bv = *(const float4*)&kp[(size_t)(k0 + lk) * L_ + n0 + ln];
        __syncthreads();
        *(float4*)&As[lk][ln] = av;
        *(float4*)&Bs[lk][ln] = bv;
        __syncthreads();
#pragma unroll
        for (int kk = 0; kk < 8; kk++) {
            float a[8], bb[8];
            *(float4*)&a[0]  = *(const float4*)&As[kk][ty * 8];
            *(float4*)&a[4]  = *(const float4*)&As[kk][ty * 8 + 4];
            *(float4*)&bb[0] = *(const float4*)&Bs[kk][tx * 8];
            *(float4*)&bb[4] = *(const float4*)&Bs[kk][tx * 8 + 4];
#pragma unroll
            for (int i = 0; i < 8; i++)
#pragma unroll
                for (int j = 0; j < 8; j++)
                    acc[i][j] = fmaf(a[i], bb[j], acc[i][j]);
        }
    }

    const float scale = 0.125f;   // D^-0.5
#pragma unroll
    for (int i = 0; i < 8; i++) {
        size_t base = (size_t)(m0 + ty * 8 + i) * L_ + n0 + tx * 8;
#pragma unroll
        for (int v = 0; v < 2; v++) {
            float4 o;
            o.x = acc[i][v * 4 + 0] * scale; o.y = acc[i][v * 4 + 1] * scale;
            o.z = acc[i][v * 4 + 2] * scale; o.w = acc[i][v * 4 + 3] * scale;
            *(float4*)&Sp[base + v * 4] = o;
        }
    }
}

// ---------------- 4) row softmax over 2048 ----------------------------------
__global__ __launch_bounds__(256) void softmax_kernel()
{
    size_t row = blockIdx.x;
    float* p = g_scores + row * L_;
    int tid = threadIdx.x;
    float v[8];
    float mx = -1e30f;
#pragma unroll
    for (int i = 0; i < 8; i++) {
        v[i] = p[tid + i * 256];
        mx = fmaxf(mx, v[i]);
    }
    __shared__ float red[256];
    red[tid] = mx; __syncthreads();
    for (int off = 128; off > 0; off >>= 1) {
        if (tid < off) red[tid] = fmaxf(red[tid], red[tid + off]);
        __syncthreads();
    }
    mx = red[0];
    __syncthreads();
    float sum = 0.f;
#pragma unroll
    for (int i = 0; i < 8; i++) {
        v[i] = fast_exp(v[i] - mx);
        sum += v[i];
    }
    red[tid] = sum; __syncthreads();
    for (int off = 128; off > 0; off >>= 1) {
        if (tid < off) red[tid] += red[tid + off];
        __syncthreads();
    }
    float inv = 1.0f / red[0];
#pragma unroll
    for (int i = 0; i < 8; i++) p[tid + i * 256] = v[i] * inv;
}

// ---------------- 5) AV: out[z][d][l] = sum_k P[l][k] * V[d][k] -------------
__global__ __launch_bounds__(256) void av_kernel()
{
    int z = blockIdx.z;
    int b = z / H_, h = z % H_;
    const float* vp = g_qkv + (size_t)b * 3 * C_ * L_ + (size_t)(2 * C_ + h * D_) * L_;
    const float* Pp = g_scores + (size_t)z * L_ * L_;
    float* op = g_att + (size_t)b * C_ * L_ + (size_t)(h * D_) * L_;

    int n0 = blockIdx.x * 128;
    __shared__ float As[8][64];     // V tile: k x d
    __shared__ float Bs[8][128];    // P^T tile: k x l

    int tid = threadIdx.x;
    int tx = tid % 32, ty = tid / 32;        // m = ty*8.., n = tx*4..
    int am = tid / 4,  ak = (tid % 4) * 2;   // A: 64 d x 8 k  (float2)
    int bn = tid / 2,  bk = (tid % 2) * 4;   // B: 128 l x 8 k (float4, transposed store)

    float acc[8][4];
#pragma unroll
    for (int i = 0; i < 8; i++)
#pragma unroll
        for (int j = 0; j < 4; j++) acc[i][j] = 0.f;

    for (int k0 = 0; k0 < L_; k0 += 8) {
        float2 av = *(const float2*)&vp[(size_t)am * L_ + k0 + ak];
        float4 bv = *(const float4*)&Pp[(size_t)(n0 + bn) * L_ + k0 + bk];
        __syncthreads();
        As[ak + 0][am] = av.x; As[ak + 1][am] = av.y;
        Bs[bk + 0][bn] = bv.x; Bs[bk + 1][bn] = bv.y;
        Bs[bk + 2][bn] = bv.z; Bs[bk + 3][bn] = bv.w;
        __syncthreads();
#pragma unroll
        for (int kk = 0; kk < 8; kk++) {
            float a[8], bb[4];
            *(float4*)&a[0] = *(const float4*)&As[kk][ty * 8];
            *(float4*)&a[4] = *(const float4*)&As[kk][ty * 8 + 4];
            *(float4*)&bb[0] = *(const float4*)&Bs[kk][tx * 4];
#pragma unroll
            for (int i = 0; i < 8; i++)
#pragma unroll
                for (int j = 0; j < 4; j++)
                    acc[i][j] = fmaf(a[i], bb[j], acc[i][j]);
        }
    }

#pragma unroll
    for (int i = 0; i < 8; i++) {
        size_t base = (size_t)(ty * 8 + i) * L_ + n0 + tx * 4;
        float4 o;
        o.x = acc[i][0]; o.y = acc[i][1]; o.z = acc[i][2]; o.w = acc[i][3];
        *(float4*)&op[base] = o;
    }
}

// ---------------- launch -----------------------------------------------------
extern "C" void kernel_launch(void* const* d_in, const int* in_sizes, int n_in,
                              void* d_out, int out_size)
{
    const float* x      = (const float*)d_in[0];
    const float* norm_w = (const float*)d_in[1];
    const float* norm_b = (const float*)d_in[2];
    const float* qkv_w  = (const float*)d_in[3];
    const float* qkv_b  = (const float*)d_in[4];
    const float* proj_w = (const float*)d_in[5];
    const float* proj_b = (const float*)d_in[6];
    float* out = (float*)d_out;

    float* qkv_ptr; cudaGetSymbolAddress((void**)&qkv_ptr, g_qkv);
    float* att_ptr; cudaGetSymbolAddress((void**)&att_ptr, g_att);

    // 1) groupnorm stats -> per-channel affine
    gn_stats_kernel<<<B_ * G_, 256>>>(x, norm_w, norm_b);

    // 2) qkv = W_qkv @ gn(x) + b   (fold=true)
    {
        dim3 grid(L_ / 128, (3 * C_) / 128, B_);
        sgemm_wx_kernel<true, false><<<grid, 256>>>(
            qkv_w, x, qkv_b, nullptr, qkv_ptr, 3 * C_, L_, C_);
    }

    // 3) scores
    {
        dim3 grid(L_ / 128, L_ / 128, B_ * H_);
        scores_kernel<<<grid, 256>>>();
    }

    // 4) softmax
    softmax_kernel<<<B_ * H_ * L_, 256>>>();

    // 5) attn @ V
    {
        dim3 grid(L_ / 128, 1, B_ * H_);
        av_kernel<<<grid, 256>>>();
    }

    // 6) proj + bias + residual
    {
        dim3 grid(L_ / 128, C_ / 128, B_);
        sgemm_wx_kernel<false, true><<<grid, 256>>>(
            proj_w, att_ptr, proj_b, x, out, C_, L_, C_);
    }
}

// round 2
// speedup vs baseline: 1.0011x; 1.0011x over previous
#include <cuda_runtime.h>
#include <math.h>

#define B_ 4
#define C_ 512
#define L_ 2048
#define H_ 8
#define D_ 64
#define G_ 8
#define CPG_ (C_/G_)          // 64 channels per group
#define EPS_ 1e-5f

// ---------------- scratch (static device allocations; no cudaMalloc) --------
__device__ float g_s[B_ * C_];                         // per-channel scale (w*rstd)
__device__ float g_t[B_ * C_];                         // per-channel shift
__device__ float g_qkv[(size_t)B_ * 3 * C_ * L_];      // 50 MB
__device__ float g_scores[(size_t)B_ * H_ * L_ * L_];  // 537 MB
__device__ float g_att[(size_t)B_ * C_ * L_];          // 17 MB

// ---------------- fast exp (avoid MUFU bottleneck) --------------------------
__device__ __forceinline__ float fast_exp(float x) {
    float z = x * 1.4426950408889634f;       // x * log2(e)
    z = fmaxf(z, -126.0f);
    float zi = rintf(z);
    int   i  = (int)zi;
    float y  = (z - zi) * 0.6931471805599453f;   // |y| <= 0.347
    float r  = 8.3333333e-3f;                    // 1/120
    r = fmaf(r, y, 4.1666667e-2f);               // 1/24
    r = fmaf(r, y, 1.6666667e-1f);               // 1/6
    r = fmaf(r, y, 0.5f);
    r = fmaf(r, y, 1.0f);
    r = fmaf(r, y, 1.0f);                        // e^y
    return __int_as_float(__float_as_int(r) + (i << 23));  // * 2^i
}

// ---------------- 1) GroupNorm stats -> per-channel affine ------------------
__global__ __launch_bounds__(256) void gn_stats_kernel(
    const float* __restrict__ x, const float* __restrict__ nw,
    const float* __restrict__ nb)
{
    int bg = blockIdx.x;
    int b = bg / G_, g = bg % G_;
    const float* xp = x + ((size_t)b * C_ + (size_t)g * CPG_) * L_;
    const int NE = CPG_ * L_;                     // 131072
    float sum = 0.f, sq = 0.f;
    for (int i = threadIdx.x; i < NE; i += 256) {
        float v = xp[i];
        sum += v; sq = fmaf(v, v, sq);
    }
    __shared__ float ssum[256], ssq[256];
    ssum[threadIdx.x] = sum; ssq[threadIdx.x] = sq;
    __syncthreads();
    for (int off = 128; off > 0; off >>= 1) {
        if (threadIdx.x < off) {
            ssum[threadIdx.x] += ssum[threadIdx.x + off];
            ssq[threadIdx.x]  += ssq[threadIdx.x + off];
        }
        __syncthreads();
    }
    float mean = ssum[0] * (1.0f / NE);
    float var  = ssq[0] * (1.0f / NE) - mean * mean;
    float rstd = rsqrtf(var + EPS_);
    if (threadIdx.x < CPG_) {
        int c = g * CPG_ + threadIdx.x;
        float s = nw[c] * rstd;
        g_s[b * C_ + c] = s;
        g_t[b * C_ + c] = nb[c] - mean * s;
    }
}

// ---------------- 2) SGEMM  C[b] = A(MxK,row) * B[b](KxN,row) + bias --------
// FOLD: B-operand element = x*s[c]+t[c] (groupnorm folded in)
// RESID: epilogue adds resid[b][m][n]
template<bool FOLD, bool RESID>
__global__ __launch_bounds__(256) void sgemm_wx_kernel(
    const float* __restrict__ A, const float* __restrict__ Bm,
    const float* __restrict__ bias, const float* __restrict__ resid,
    float* __restrict__ Cm, int M, int N, int K)
{
    int bz = blockIdx.z;
    const float* Bp = Bm + (size_t)bz * K * N;
    float*       Cp = Cm + (size_t)bz * M * N;
    const float* Rp = RESID ? (resid + (size_t)bz * M * N) : nullptr;
    const float* sp = FOLD ? (g_s + bz * C_) : nullptr;
    const float* tp = FOLD ? (g_t + bz * C_) : nullptr;

    int m0 = blockIdx.y * 128, n0 = blockIdx.x * 128;
    __shared__ float As[8][128];
    __shared__ float Bs[8][128];

    int tid = threadIdx.x;
    int tx = tid % 16, ty = tid / 16;     // 8x8 micro-tile
    int ar = tid / 2,  ac = (tid % 2) * 4;      // A: 128 rows x 8 k
    int bk = tid / 32, bn = (tid % 32) * 4;     // B: 8 k x 128 n

    float acc[8][8];
#pragma unroll
    for (int i = 0; i < 8; i++)
#pragma unroll
        for (int j = 0; j < 8; j++) acc[i][j] = 0.f;

    for (int k0 = 0; k0 < K; k0 += 8) {
        float4 av = *(const float4*)&A[(size_t)(m0 + ar) * K + k0 + ac];
        float4 bv = *(const float4*)&Bp[(size_t)(k0 + bk) * N + n0 + bn];
        if (FOLD) {
            float ss = sp[k0 + bk], tt = tp[k0 + bk];
            bv.x = fmaf(bv.x, ss, tt); bv.y = fmaf(bv.y, ss, tt);
            bv.z = fmaf(bv.z, ss, tt); bv.w = fmaf(bv.w, ss, tt);
        }
        __syncthreads();
        As[ac + 0][ar] = av.x; As[ac + 1][ar] = av.y;
        As[ac + 2][ar] = av.z; As[ac + 3][ar] = av.w;
        *(float4*)&Bs[bk][bn] = bv;
        __syncthreads();
#pragma unroll
        for (int kk = 0; kk < 8; kk++) {
            float a[8], bb[8];
            *(float4*)&a[0]  = *(const float4*)&As[kk][ty * 8];
            *(float4*)&a[4]  = *(const float4*)&As[kk][ty * 8 + 4];
            *(float4*)&bb[0] = *(const float4*)&Bs[kk][tx * 8];
            *(float4*)&bb[4] = *(const float4*)&Bs[kk][tx * 8 + 4];
#pragma unroll
            for (int i = 0; i < 8; i++)
#pragma unroll
                for (int j = 0; j < 8; j++)
                    acc[i][j] = fmaf(a[i], bb[j], acc[i][j]);
        }
    }

#pragma unroll
    for (int i = 0; i < 8; i++) {
        int m = m0 + ty * 8 + i;
        float bvv = bias[m];
        size_t base = (size_t)m * N + n0 + tx * 8;
#pragma unroll
        for (int v = 0; v < 2; v++) {
            float4 o;
            o.x = acc[i][v * 4 + 0] + bvv; o.y = acc[i][v * 4 + 1] + bvv;
            o.z = acc[i][v * 4 + 2] + bvv; o.w = acc[i][v * 4 + 3] + bvv;
            if (RESID) {
                float4 r = *(const float4*)&Rp[base + v * 4];
                o.x += r.x; o.y += r.y; o.z += r.z; o.w += r.w;
            }
            *(float4*)&Cp[base + v * 4] = o;
        }
    }
}

// ---------------- 3) scores: S[z][l][k] = scale * sum_d q[d][l]*k[d][k] -----
__global__ __launch_bounds__(256) void scores_kernel()
{
    int z = blockIdx.z;
    int b = z / H_, h = z % H_;
    const float* qp = g_qkv + (size_t)b * 3 * C_ * L_ + (size_t)(h * D_) * L_;
    const float* kp = qp + (size_t)C_ * L_;
    float* Sp = g_scores + (size_t)z * L_ * L_;

    int m0 = blockIdx.y * 128, n0 = blockIdx.x * 128;
    __shared__ float As[8][128];
    __shared__ float Bs[8][128];

    int tid = threadIdx.x;
    int tx = tid % 16, ty = tid / 16;
    int lk = tid / 32, ln = (tid % 32) * 4;

    float acc[8][8];
#pragma unroll
    for (int i = 0; i < 8; i++)
#pragma unroll
        for (int j = 0; j < 8; j++) acc[i][j] = 0.f;

    for (int k0 = 0; k0 < D_; k0 += 8) {
        float4 av = *(const float4*)&qp[(size_t)(k0 + lk) * L_ + m0 + ln];
        float4 bv = *(const float4*)&kp[(size_t)(k0 + lk) * L_ + n0 + ln];
        __syncthreads();
        *(float4*)&As[lk][ln] = av;
        *(float4*)&Bs[lk][ln] = bv;
        __syncthreads();
#pragma unroll
        for (int kk = 0; kk < 8; kk++) {
            float a[8], bb[8];
            *(float4*)&a[0]  = *(const float4*)&As[kk][ty * 8];
            *(float4*)&a[4]  = *(const float4*)&As[kk][ty * 8 + 4];
            *(float4*)&bb[0] = *(const float4*)&Bs[kk][tx * 8];
            *(float4*)&bb[4] = *(const float4*)&Bs[kk][tx * 8 + 4];
#pragma unroll
            for (int i = 0; i < 8; i++)
#pragma unroll
                for (int j = 0; j < 8; j++)
                    acc[i][j] = fmaf(a[i], bb[j], acc[i][j]);
        }
    }

    const float scale = 0.125f;   // D^-0.5
#pragma unroll
    for (int i = 0; i < 8; i++) {
        size_t base = (size_t)(m0 + ty * 8 + i) * L_ + n0 + tx * 8;
#pragma unroll
        for (int v = 0; v < 2; v++) {
            float4 o;
            o.x = acc[i][v * 4 + 0] * scale; o.y = acc[i][v * 4 + 1] * scale;
            o.z = acc[i][v * 4 + 2] * scale; o.w = acc[i][v * 4 + 3] * scale;
            *(float4*)&Sp[base + v * 4] = o;
        }
    }
}

// ---------------- 4) row softmax over 2048 ----------------------------------
__global__ __launch_bounds__(256) void softmax_kernel()
{
    size_t row = blockIdx.x;
    float* p = g_scores + row * L_;
    int tid = threadIdx.x;
    float v[8];
    float mx = -1e30f;
#pragma unroll
    for (int i = 0; i < 8; i++) {
        v[i] = p[tid + i * 256];
        mx = fmaxf(mx, v[i]);
    }
    __shared__ float red[256];
    red[tid] = mx; __syncthreads();
    for (int off = 128; off > 0; off >>= 1) {
        if (tid < off) red[tid] = fmaxf(red[tid], red[tid + off]);
        __syncthreads();
    }
    mx = red[0];
    __syncthreads();
    float sum = 0.f;
#pragma unroll
    for (int i = 0; i < 8; i++) {
        v[i] = fast_exp(v[i] - mx);
        sum += v[i];
    }
    red[tid] = sum; __syncthreads();
    for (int off = 128; off > 0; off >>= 1) {
        if (tid < off) red[tid] += red[tid + off];
        __syncthreads();
    }
    float inv = 1.0f / red[0];
#pragma unroll
    for (int i = 0; i < 8; i++) p[tid + i * 256] = v[i] * inv;
}

// ---------------- 5) AV: out[z][d][l] = sum_k P[l][k] * V[d][k] -------------
__global__ __launch_bounds__(256) void av_kernel()
{
    int z = blockIdx.z;
    int b = z / H_, h = z % H_;
    const float* vp = g_qkv + (size_t)b * 3 * C_ * L_ + (size_t)(2 * C_ + h * D_) * L_;
    const float* Pp = g_scores + (size_t)z * L_ * L_;
    float* op = g_att + (size_t)b * C_ * L_ + (size_t)(h * D_) * L_;

    int n0 = blockIdx.x * 128;
    __shared__ float As[8][64];     // V tile: k x d
    __shared__ float Bs[8][128];    // P^T tile: k x l

    int tid = threadIdx.x;
    int tx = tid % 32, ty = tid / 32;        // m = ty*8.., n = tx*4..
    int am = tid / 4,  ak = (tid % 4) * 2;   // A: 64 d x 8 k  (float2)
    int bn = tid / 2,  bk = (tid % 2) * 4;   // B: 128 l x 8 k (float4, transposed store)

    float acc[8][4];
#pragma unroll
    for (int i = 0; i < 8; i++)
#pragma unroll
        for (int j = 0; j < 4; j++) acc[i][j] = 0.f;

    for (int k0 = 0; k0 < L_; k0 += 8) {
        float2 av = *(const float2*)&vp[(size_t)am * L_ + k0 + ak];
        float4 bv = *(const float4*)&Pp[(size_t)(n0 + bn) * L_ + k0 + bk];
        __syncthreads();
        As[ak + 0][am] = av.x; As[ak + 1][am] = av.y;
        Bs[bk + 0][bn] = bv.x; Bs[bk + 1][bn] = bv.y;
        Bs[bk + 2][bn] = bv.z; Bs[bk + 3][bn] = bv.w;
        __syncthreads();
#pragma unroll
        for (int kk = 0; kk < 8; kk++) {
            float a[8], bb[4];
            *(float4*)&a[0] = *(const float4*)&As[kk][ty * 8];
            *(float4*)&a[4] = *(const float4*)&As[kk][ty * 8 + 4];
            *(float4*)&bb[0] = *(const float4*)&Bs[kk][tx * 4];
#pragma unroll
            for (int i = 0; i < 8; i++)
#pragma unroll
                for (int j = 0; j < 4; j++)
                    acc[i][j] = fmaf(a[i], bb[j], acc[i][j]);
        }
    }

#pragma unroll
    for (int i = 0; i < 8; i++) {
        size_t base = (size_t)(ty * 8 + i) * L_ + n0 + tx * 4;
        float4 o;
        o.x = acc[i][0]; o.y = acc[i][1]; o.z = acc[i][2]; o.w = acc[i][3];
        *(float4*)&op[base] = o;
    }
}

// ---------------- launch -----------------------------------------------------
extern "C" void kernel_launch(void* const* d_in, const int* in_sizes, int n_in,
                              void* d_out, int out_size)
{
    const float* x      = (const float*)d_in[0];
    const float* norm_w = (const float*)d_in[1];
    const float* norm_b = (const float*)d_in[2];
    const float* qkv_w  = (const float*)d_in[3];
    const float* qkv_b  = (const float*)d_in[4];
    const float* proj_w = (const float*)d_in[5];
    const float* proj_b = (const float*)d_in[6];
    float* out = (float*)d_out;

    float* qkv_ptr; cudaGetSymbolAddress((void**)&qkv_ptr, g_qkv);
    float* att_ptr; cudaGetSymbolAddress((void**)&att_ptr, g_att);

    // 1) groupnorm stats -> per-channel affine
    gn_stats_kernel<<<B_ * G_, 256>>>(x, norm_w, norm_b);

    // 2) qkv = W_qkv @ gn(x) + b   (fold=true)
    {
        dim3 grid(L_ / 128, (3 * C_) / 128, B_);
        sgemm_wx_kernel<true, false><<<grid, 256>>>(
            qkv_w, x, qkv_b, nullptr, qkv_ptr, 3 * C_, L_, C_);
    }

    // 3) scores
    {
        dim3 grid(L_ / 128, L_ / 128, B_ * H_);
        scores_kernel<<<grid, 256>>>();
    }

    // 4) softmax
    softmax_kernel<<<B_ * H_ * L_, 256>>>();

    // 5) attn @ V
    {
        dim3 grid(L_ / 128, 1, B_ * H_);
        av_kernel<<<grid, 256>>>();
    }

    // 6) proj + bias + residual
    {
        dim3 grid(L_ / 128, C_ / 128, B_);
        sgemm_wx_kernel<false, true><<<grid, 256>>>(
            proj_w, att_ptr, proj_b, x, out, C_, L_, C_);
    }
}